// round 12
// baseline (speedup 1.0000x reference)
#include <cuda_runtime.h>
#include <cuda_bf16.h>
#include <math.h>
#include <stdint.h>

#define SQ   2048
#define HID  768
#define NH   12
#define HD   64
#define NF   128
#define KE   192
#define NW   (HID * HID)

// ring engine: 3 slots x (Ah/Al/Bh/Bl 8K each)
#define SLOT_PR   32768
#define SMEM_PR   (3 * SLOT_PR)                  // 98304
// scores v2: A panel (hi 48K + lo 16K) + B ring 3 x 16K = 112K
#define SMEM_SC2  114688
// context kernel smem: 4 slots x (Ah 8K + Al 8K + Bh 4K + Bl 4K)
#define SLOT_CTX  24576
#define SMEM_CTX  (4 * SLOT_CTX)                 // 98304

// ---------------- device scratch ----------------
__device__ float g_Q [NH * SQ * HD];
__device__ float g_K [NH * SQ * HD];
__device__ __align__(16) __nv_bfloat16 g_Xh [SQ * HID];
__device__ __align__(16) __nv_bfloat16 g_Xl [SQ * HID];
__device__ __align__(16) __nv_bfloat16 g_Wbh[4 * NW];     // Wq,Wk,Wv,Wo hi
__device__ __align__(16) __nv_bfloat16 g_Wbl[4 * NW];     // lo
__device__ __align__(16) __nv_bfloat16 g_Qeh[NH * SQ * KE];
__device__ __align__(16) __nv_bfloat16 g_Qel[NH * SQ * KE];
__device__ __align__(16) __nv_bfloat16 g_Keh[NH * SQ * KE];
__device__ __align__(16) __nv_bfloat16 g_Kel[NH * SQ * KE];
__device__ __align__(16) __nv_bfloat16 g_Vth[NH * HD * SQ];
__device__ __align__(16) __nv_bfloat16 g_Vtl[NH * HD * SQ];
__device__ __align__(16) __nv_bfloat16 g_Wh [(size_t)NH * SQ * SQ];
__device__ __align__(16) __nv_bfloat16 g_Wl [(size_t)NH * SQ * SQ];
__device__ __align__(16) __nv_bfloat16 g_Ctxh[SQ * HID];
__device__ __align__(16) __nv_bfloat16 g_Ctxl[SQ * HID];
__device__ __align__(16) float g_Wsc[(size_t)NH * SQ * SQ];

// ---------------- low-level helpers ----------------
__device__ __forceinline__ uint32_t smem_u32(const void* p) {
    return (uint32_t)__cvta_generic_to_shared(p);
}
__device__ __forceinline__ void ldm4(uint32_t r[4], uint32_t addr) {
    asm volatile("ldmatrix.sync.aligned.m8n8.x4.shared.b16 {%0,%1,%2,%3}, [%4];"
                 : "=r"(r[0]), "=r"(r[1]), "=r"(r[2]), "=r"(r[3]) : "r"(addr));
}
__device__ __forceinline__ void mma16(float c[4], const uint32_t a[4], const uint32_t b[2]) {
    asm volatile(
        "mma.sync.aligned.m16n8k16.row.col.f32.bf16.bf16.f32 "
        "{%0,%1,%2,%3},{%4,%5,%6,%7},{%8,%9},{%0,%1,%2,%3};\n"
        : "+f"(c[0]), "+f"(c[1]), "+f"(c[2]), "+f"(c[3])
        : "r"(a[0]), "r"(a[1]), "r"(a[2]), "r"(a[3]), "r"(b[0]), "r"(b[1]));
}
__device__ __forceinline__ void cpa16(uint32_t saddr, const void* g) {
    asm volatile("cp.async.cg.shared.global [%0], [%1], 16;\n" :: "r"(saddr), "l"(g));
}
__device__ __forceinline__ void cp_commit() {
    asm volatile("cp.async.commit_group;\n");
}
template<int N> __device__ __forceinline__ void cp_wait() {
    asm volatile("cp.async.wait_group %0;\n" :: "n"(N));
}
__device__ __forceinline__ void split2(float v, __nv_bfloat16& h, __nv_bfloat16& l) {
    h = __float2bfloat16_rn(v);
    l = __float2bfloat16_rn(v - __bfloat162float(h));
}

// =======================================================================
// K0: prep — split X and the 4 weight matrices into bf16 hi/lo.
// =======================================================================
#define PREP_N4 ((SQ * HID + 4 * NW) / 4)
__global__ __launch_bounds__(256) void k_prep(const float* __restrict__ X,
    const float* __restrict__ Wq, const float* __restrict__ Wk,
    const float* __restrict__ Wv, const float* __restrict__ Wo)
{
    const int i = blockIdx.x * 256 + threadIdx.x;
    if (i >= PREP_N4) return;
    const int NX4 = SQ * HID / 4, NW4 = NW / 4;
    const float* src;
    __nv_bfloat16 *dh, *dl;
    int j = i;
    if (j < NX4) { src = X; dh = g_Xh; dl = g_Xl; }
    else {
        j -= NX4;
        const int z = j / NW4;
        j -= z * NW4;
        src = (z == 0) ? Wq : (z == 1) ? Wk : (z == 2) ? Wv : Wo;
        dh = g_Wbh + (size_t)z * NW; dl = g_Wbl + (size_t)z * NW;
    }
    float4 v = *(const float4*)(src + (size_t)j * 4);
    __nv_bfloat162 h01 = __floats2bfloat162_rn(v.x, v.y);
    __nv_bfloat162 h23 = __floats2bfloat162_rn(v.z, v.w);
    float2 f01 = __bfloat1622float2(h01), f23 = __bfloat1622float2(h23);
    *(__nv_bfloat162*)(dh + (size_t)j * 4)     = h01;
    *(__nv_bfloat162*)(dh + (size_t)j * 4 + 2) = h23;
    *(__nv_bfloat162*)(dl + (size_t)j * 4)     = __floats2bfloat162_rn(v.x - f01.x, v.y - f01.y);
    *(__nv_bfloat162*)(dl + (size_t)j * 4 + 2) = __floats2bfloat162_rn(v.z - f23.x, v.w - f23.y);
}

// =======================================================================
// Generic pre-split bf16 ABt ring engine. 3 slots, prefetch distance 2.
// block 128x128, 8 warps (2m x 4n), warp tile 64x32.
// =======================================================================
__device__ __forceinline__ void tc_abt_ring(const __nv_bfloat16* __restrict__ Agh,
                                            const __nv_bfloat16* __restrict__ Agl,
                                            const __nv_bfloat16* __restrict__ Bgh,
                                            const __nv_bfloat16* __restrict__ Bgl,
                                            int ld, int nCh,
                                            float acc[4][4][4])
{
    extern __shared__ char smc[];
    const int tid = threadIdx.x, w = tid >> 5, l = tid & 31;
    const int mW = (w >> 2) * 64, nW = (w & 3) * 32;
    const uint32_t sb = smem_u32(smc);

    auto issue = [&](int c) {
        const uint32_t slot = sb + (uint32_t)(c % 3) * SLOT_PR;
#pragma unroll
        for (int it = 0; it < 2; it++) {
            const int id = it * 256 + tid;
            const int r = id >> 2, jc = id & 3;
            const int js = (jc + ((r >> 1) & 3)) & 3;
            const uint32_t so = (uint32_t)(r * 64 + js * 16);
            const size_t go = (size_t)r * ld + c * 32 + jc * 8;
            cpa16(slot + so,         Agh + go);
            cpa16(slot + 8192 + so,  Agl + go);
            cpa16(slot + 16384 + so, Bgh + go);
            cpa16(slot + 24576 + so, Bgl + go);
        }
        cp_commit();
    };

    issue(0); issue(1);

    const int aR0 = l & 15, aJ = l >> 4;
    const int bR0 = ((l >> 4) << 3) + (l & 7), bJ = (l >> 3) & 1;

    for (int c = 0; c < nCh; c++) {
        if (c <= nCh - 2) cp_wait<1>();
        else              cp_wait<0>();
        __syncthreads();
        const uint32_t slot = sb + (uint32_t)(c % 3) * SLOT_PR;
#pragma unroll
        for (int kk = 0; kk < 2; kk++) {
            uint32_t ah[4][4], al_[4][4], bh_[2][4], bl_[2][4];
#pragma unroll
            for (int mi = 0; mi < 4; mi++) {
                const int R = mW + mi * 16 + aR0;
                const int j = (kk << 1) | aJ;
                const int js = (j + ((R >> 1) & 3)) & 3;
                const uint32_t off = (uint32_t)(R * 64 + js * 16);
                ldm4(ah[mi],  slot + off);
                ldm4(al_[mi], slot + 8192 + off);
            }
#pragma unroll
            for (int np = 0; np < 2; np++) {
                const int R = nW + np * 16 + bR0;
                const int j = (kk << 1) | bJ;
                const int js = (j + ((R >> 1) & 3)) & 3;
                const uint32_t off = (uint32_t)(R * 64 + js * 16);
                ldm4(bh_[np], slot + 16384 + off);
                ldm4(bl_[np], slot + 24576 + off);
            }
#pragma unroll
            for (int mi = 0; mi < 4; mi++)
#pragma unroll
                for (int ni = 0; ni < 4; ni++) {
                    const int np = ni >> 1, q = (ni & 1) * 2;
                    uint32_t bhf[2] = { bh_[np][q], bh_[np][q + 1] };
                    uint32_t blf[2] = { bl_[np][q], bl_[np][q + 1] };
                    mma16(acc[mi][ni], ah[mi], bhf);
                    mma16(acc[mi][ni], ah[mi], blf);
                    mma16(acc[mi][ni], al_[mi], bhf);
                }
        }
        if (c + 2 < nCh) issue(c + 2);
    }
}

// =======================================================================
// K1: QKV projections. z=0:Q 1:K 2:V. grid (6,16,3), 256 thr
// =======================================================================
__global__ __launch_bounds__(256) void k_qkv(const float* __restrict__ bq,
    const float* __restrict__ bk, const float* __restrict__ bv)
{
    const int z = blockIdx.z;
    const float* bias = (z == 0) ? bq : (z == 1) ? bk : bv;
    const int rowBase = blockIdx.y * 128;
    const int colBase = blockIdx.x * 128;

    float acc[4][4][4];
#pragma unroll
    for (int a = 0; a < 4; a++)
#pragma unroll
        for (int b = 0; b < 4; b++)
#pragma unroll
            for (int c = 0; c < 4; c++) acc[a][b][c] = 0.f;

    tc_abt_ring(g_Xh + (size_t)rowBase * HID, g_Xl + (size_t)rowBase * HID,
                g_Wbh + (size_t)z * NW + (size_t)colBase * HID,
                g_Wbl + (size_t)z * NW + (size_t)colBase * HID,
                HID, HID / 32, acc);

    const int w = threadIdx.x >> 5, l = threadIdx.x & 31;
    const int g = l >> 2, tg = l & 3;
    const int mW = (w >> 2) * 64, nW = (w & 3) * 32;
#pragma unroll
    for (int mi = 0; mi < 4; mi++) {
#pragma unroll
        for (int ni = 0; ni < 4; ni++) {
#pragma unroll
            for (int cr = 0; cr < 4; cr++) {
                const int s = rowBase + mW + mi * 16 + g + ((cr >> 1) << 3);
                const int o = colBase + nW + ni * 8 + 2 * tg + (cr & 1);
                const float v = acc[mi][ni][cr] + bias[o];
                const int h = o >> 6, d = o & 63;
                if (z == 2) {
                    __nv_bfloat16 hi, lo; split2(v, hi, lo);
                    const size_t idx = ((size_t)h * HD + d) * SQ + s;
                    g_Vth[idx] = hi; g_Vtl[idx] = lo;
                } else if (z == 1) g_K[((size_t)h * SQ + s) * HD + d] = v;
                else               g_Q[((size_t)h * SQ + s) * HD + d] = v;
            }
        }
    }
}

// =======================================================================
// K2: RFF features. 16 rows/block, 2 syncs/row. grid (128, NH, 2), 128 thr
// =======================================================================
#define OMLD 129
#define PHI_ROWS 16

__global__ __launch_bounds__(128) void k_phi(const float* __restrict__ omega,
                                             const float* __restrict__ rffb)
{
    __shared__ float omT[HD * OMLD];
    __shared__ float qrow[2][HD];
    __shared__ float red[2][4];

    const int tid  = threadIdx.x;
    const int h    = blockIdx.y;
    const int side = blockIdx.z;
    const int lane = tid & 31, wrp = tid >> 5;

    for (int i = tid; i < NF * HD; i += 128) {
        const int f = i >> 6, d = i & 63;
        omT[d * OMLD + f] = omega[((size_t)h * NF + f) * HD + d];
    }
    const float bf = rffb[h * NF + tid];
    const float* src = (side ? g_K : g_Q) + (size_t)h * SQ * HD;
    __nv_bfloat16* eh = (side ? g_Keh : g_Qeh) + (size_t)h * SQ * KE;
    __nv_bfloat16* el = (side ? g_Kel : g_Qel) + (size_t)h * SQ * KE;
    const float qscale   = side ? 1.0f : 0.1125f;
    const float segscale = side ? 1.0f : 0.1f;

    for (int r = 0; r < PHI_ROWS; r++) {
        const int s = blockIdx.x * PHI_ROWS + r;
        const int p = r & 1;
        if (tid < 64) qrow[p][tid] = src[(size_t)s * HD + tid];
        __syncthreads();

        float dot = 0.f, qss = 0.f;
#pragma unroll 8
        for (int d = 0; d < HD; d++) {
            const float qd = qrow[p][d];
            dot += qd * omT[d * OMLD + tid];
            qss += qd * qd;
        }
        const float inv = 1.0f / (sqrtf(qss) + 1e-5f);
        const float zv = inv * dot + bf;
        const float ph = 0.125f * __cosf(zv);

        float v = ph * ph;
        for (int o = 16; o > 0; o >>= 1) v += __shfl_xor_sync(0xffffffffu, v, o);
        if (lane == 0) red[p][wrp] = v;
        __syncthreads();
        const float pn2 = red[p][0] + red[p][1] + red[p][2] + red[p][3];

        const float outv = (ph / (sqrtf(pn2) + 1e-6f)) * segscale;
        __nv_bfloat16 hi, lo;
        split2(outv, hi, lo);
        eh[(size_t)s * KE + HD + tid] = hi;
        el[(size_t)s * KE + HD + tid] = lo;
        if (tid < 64) {
            split2(qrow[p][tid] * qscale, hi, lo);
            eh[(size_t)s * KE + tid] = hi;
            el[(size_t)s * KE + tid] = lo;
        }
    }
}

// =======================================================================
// K3 v2: scores = Qe . Ke^T + mask. A panel resident (hi 6 planes + lo 2),
// B streamed through 3-slot ring. Each block: 1 row tile x 2 col tiles.
// chunks 0-1 hi/lo 3-term, chunks 2-5 single bf16. grid (8,16,12), 256 thr
// =======================================================================
__global__ __launch_bounds__(256, 2) void k_scores(const float* __restrict__ mask,
                                                   float* wts)
{
    extern __shared__ char smc[];
    float* W = wts ? wts : g_Wsc;
    const int h = blockIdx.z;
    const int rowBase = blockIdx.y * 128;
    const int colBase = blockIdx.x * 256;
    const int tid = threadIdx.x, w = tid >> 5, l = tid & 31;
    const int mW = (w >> 2) * 64, nW = (w & 3) * 32;
    const uint32_t sb = smem_u32(smc);
    const uint32_t Bbase = sb + 65536;

    const __nv_bfloat16* Agh = g_Qeh + (size_t)(h * SQ + rowBase) * KE;
    const __nv_bfloat16* Agl = g_Qel + (size_t)(h * SQ + rowBase) * KE;

    // stage A panel (part of B0's commit group)
#pragma unroll
    for (int p = 0; p < 6; p++)
#pragma unroll
        for (int it = 0; it < 2; it++) {
            const int id = it * 256 + tid;
            const int r = id >> 2, jc = id & 3;
            const int js = (jc + ((r >> 1) & 3)) & 3;
            cpa16(sb + (uint32_t)(p * 8192 + r * 64 + js * 16),
                  Agh + (size_t)r * KE + p * 32 + jc * 8);
        }
#pragma unroll
    for (int p = 0; p < 2; p++)
#pragma unroll
        for (int it = 0; it < 2; it++) {
            const int id = it * 256 + tid;
            const int r = id >> 2, jc = id & 3;
            const int js = (jc + ((r >> 1) & 3)) & 3;
            cpa16(sb + (uint32_t)(49152 + p * 8192 + r * 64 + js * 16),
                  Agl + (size_t)r * KE + p * 32 + jc * 8);
        }

    auto issueB = [&](int t) {
        const int c = t % 6, tile = t / 6;
        const uint32_t slot = Bbase + (uint32_t)(t % 3) * 16384;
        const __nv_bfloat16* Bh = g_Keh + (size_t)(h * SQ + colBase + tile * 128) * KE;
        const __nv_bfloat16* Bl = g_Kel + (size_t)(h * SQ + colBase + tile * 128) * KE;
#pragma unroll
        for (int it = 0; it < 2; it++) {
            const int id = it * 256 + tid;
            const int r = id >> 2, jc = id & 3;
            const int js = (jc + ((r >> 1) & 3)) & 3;
            const uint32_t so = (uint32_t)(r * 64 + js * 16);
            const size_t go = (size_t)r * KE + c * 32 + jc * 8;
            cpa16(slot + so, Bh + go);
            if (c < 2) cpa16(slot + 8192 + so, Bl + go);
        }
        cp_commit();
    };

    issueB(0);   // commits A panel + B chunk 0
    issueB(1);

    float acc[4][4][4];
#pragma unroll
    for (int a = 0; a < 4; a++)
#pragma unroll
        for (int b = 0; b < 4; b++)
#pragma unroll
            for (int c = 0; c < 4; c++) acc[a][b][c] = 0.f;

    const int aR0 = l & 15, aJ = l >> 4;
    const int bR0 = ((l >> 4) << 3) + (l & 7), bJ = (l >> 3) & 1;
    const int g = l >> 2, tg = l & 3;

    for (int t = 0; t < 12; t++) {
        const int c = t % 6;
        if (t <= 10) cp_wait<1>();
        else         cp_wait<0>();
        __syncthreads();
        const uint32_t bslot  = Bbase + (uint32_t)(t % 3) * 16384;
        const uint32_t aplane  = sb + (uint32_t)c * 8192;
        const uint32_t aplaneL = sb + 49152 + (uint32_t)c * 8192;
#pragma unroll
        for (int kk = 0; kk < 2; kk++) {
            uint32_t ah[4][4], bh_[2][4];
#pragma unroll
            for (int mi = 0; mi < 4; mi++) {
                const int R = mW + mi * 16 + aR0;
                const int j = (kk << 1) | aJ;
                const int js = (j + ((R >> 1) & 3)) & 3;
                ldm4(ah[mi], aplane + (uint32_t)(R * 64 + js * 16));
            }
#pragma unroll
            for (int np = 0; np < 2; np++) {
                const int R = nW + np * 16 + bR0;
                const int j = (kk << 1) | bJ;
                const int js = (j + ((R >> 1) & 3)) & 3;
                ldm4(bh_[np], bslot + (uint32_t)(R * 64 + js * 16));
            }
            if (c < 2) {
                uint32_t al_[4][4], bl_[2][4];
#pragma unroll
                for (int mi = 0; mi < 4; mi++) {
                    const int R = mW + mi * 16 + aR0;
                    const int j = (kk << 1) | aJ;
                    const int js = (j + ((R >> 1) & 3)) & 3;
                    ldm4(al_[mi], aplaneL + (uint32_t)(R * 64 + js * 16));
                }
#pragma unroll
                for (int np = 0; np < 2; np++) {
                    const int R = nW + np * 16 + bR0;
                    const int j = (kk << 1) | bJ;
                    const int js = (j + ((R >> 1) & 3)) & 3;
                    ldm4(bl_[np], bslot + 8192 + (uint32_t)(R * 64 + js * 16));
                }
#pragma unroll
                for (int mi = 0; mi < 4; mi++)
#pragma unroll
                    for (int ni = 0; ni < 4; ni++) {
                        const int np = ni >> 1, q = (ni & 1) * 2;
                        uint32_t bhf[2] = { bh_[np][q], bh_[np][q + 1] };
                        uint32_t blf[2] = { bl_[np][q], bl_[np][q + 1] };
                        mma16(acc[mi][ni], ah[mi], bhf);
                        mma16(acc[mi][ni], ah[mi], blf);
                        mma16(acc[mi][ni], al_[mi], bhf);
                    }
            } else {
#pragma unroll
                for (int mi = 0; mi < 4; mi++)
#pragma unroll
                    for (int ni = 0; ni < 4; ni++) {
                        const int np = ni >> 1, q = (ni & 1) * 2;
                        uint32_t bhf[2] = { bh_[np][q], bh_[np][q + 1] };
                        mma16(acc[mi][ni], ah[mi], bhf);
                    }
            }
        }
        if (t + 2 < 12) issueB(t + 2);

        if (c == 5) {
            // epilogue for this col tile, then reset acc
            const int colT = colBase + (t / 6) * 128;
            float* Wh = W + (size_t)h * SQ * SQ;
#pragma unroll
            for (int mi = 0; mi < 4; mi++) {
#pragma unroll
                for (int ni = 0; ni < 4; ni++) {
                    const int t0 = colT + nW + ni * 8 + 2 * tg;
                    const float mk0 = (mask[t0] - 1.0f) * 10000.0f;
                    const float mk1 = (mask[t0 + 1] - 1.0f) * 10000.0f;
#pragma unroll
                    for (int half = 0; half < 2; half++) {
                        const int s = rowBase + mW + mi * 16 + g + half * 8;
                        float2 v = make_float2(acc[mi][ni][half * 2 + 0] + mk0,
                                               acc[mi][ni][half * 2 + 1] + mk1);
                        *(float2*)(Wh + (size_t)s * SQ + t0) = v;
                        acc[mi][ni][half * 2 + 0] = 0.f;
                        acc[mi][ni][half * 2 + 1] = 0.f;
                    }
                }
            }
        }
    }
}

// =======================================================================
// K4: row softmax, fp32 out + bf16 hi/lo copies. grid (NH*SQ), 256 thr
// =======================================================================
__global__ __launch_bounds__(256) void k_softmax(float* wts)
{
    __shared__ float red[8];
    float* W = wts ? wts : g_Wsc;
    float4* p = (float4*)(W + (size_t)blockIdx.x * SQ);
    __nv_bfloat16* wh = g_Wh + (size_t)blockIdx.x * SQ;
    __nv_bfloat16* wl = g_Wl + (size_t)blockIdx.x * SQ;
    const int tid = threadIdx.x;

    float4 v0 = p[tid];
    float4 v1 = p[tid + 256];
    float m = fmaxf(fmaxf(fmaxf(v0.x, v0.y), fmaxf(v0.z, v0.w)),
                    fmaxf(fmaxf(v1.x, v1.y), fmaxf(v1.z, v1.w)));
    for (int o = 16; o > 0; o >>= 1) m = fmaxf(m, __shfl_xor_sync(0xffffffffu, m, o));
    if ((tid & 31) == 0) red[tid >> 5] = m;
    __syncthreads();
    m = red[0];
#pragma unroll
    for (int i = 1; i < 8; i++) m = fmaxf(m, red[i]);
    __syncthreads();

    v0.x = __expf(v0.x - m); v0.y = __expf(v0.y - m);
    v0.z = __expf(v0.z - m); v0.w = __expf(v0.w - m);
    v1.x = __expf(v1.x - m); v1.y = __expf(v1.y - m);
    v1.z = __expf(v1.z - m); v1.w = __expf(v1.w - m);
    float s = v0.x + v0.y + v0.z + v0.w + v1.x + v1.y + v1.z + v1.w;
    for (int o = 16; o > 0; o >>= 1) s += __shfl_xor_sync(0xffffffffu, s, o);
    if ((tid & 31) == 0) red[tid >> 5] = s;
    __syncthreads();
    s = red[0] + red[1] + red[2] + red[3] + red[4] + red[5] + red[6] + red[7];
    const float inv = 1.0f / s;

    v0.x *= inv; v0.y *= inv; v0.z *= inv; v0.w *= inv;
    v1.x *= inv; v1.y *= inv; v1.z *= inv; v1.w *= inv;
    p[tid] = v0;
    p[tid + 256] = v1;

    {
        __nv_bfloat162 h01 = __floats2bfloat162_rn(v0.x, v0.y);
        __nv_bfloat162 h23 = __floats2bfloat162_rn(v0.z, v0.w);
        float2 f01 = __bfloat1622float2(h01), f23 = __bfloat1622float2(h23);
        *(__nv_bfloat162*)(wh + tid * 4)     = h01;
        *(__nv_bfloat162*)(wh + tid * 4 + 2) = h23;
        *(__nv_bfloat162*)(wl + tid * 4)     = __floats2bfloat162_rn(v0.x - f01.x, v0.y - f01.y);
        *(__nv_bfloat162*)(wl + tid * 4 + 2) = __floats2bfloat162_rn(v0.z - f23.x, v0.w - f23.y);
        h01 = __floats2bfloat162_rn(v1.x, v1.y);
        h23 = __floats2bfloat162_rn(v1.z, v1.w);
        f01 = __bfloat1622float2(h01); f23 = __bfloat1622float2(h23);
        *(__nv_bfloat162*)(wh + (tid + 256) * 4)     = h01;
        *(__nv_bfloat162*)(wh + (tid + 256) * 4 + 2) = h23;
        *(__nv_bfloat162*)(wl + (tid + 256) * 4)     = __floats2bfloat162_rn(v1.x - f01.x, v1.y - f01.y);
        *(__nv_bfloat162*)(wl + (tid + 256) * 4 + 2) = __floats2bfloat162_rn(v1.z - f23.x, v1.w - f23.y);
    }
}

// =======================================================================
// K5: context = W . Vt^T -> bf16 hi/lo Ctx. cp.async 4-slot ring. grid (16, NH)
// =======================================================================
__global__ __launch_bounds__(256) void k_context()
{
    extern __shared__ char smc[];
    const int h = blockIdx.y;
    const int rowBase = blockIdx.x * 128;
    const int tid = threadIdx.x, w = tid >> 5, l = tid & 31;
    const int mW = (w >> 1) * 32, nW = (w & 1) * 32;
    const uint32_t sb = smem_u32(smc);

    const __nv_bfloat16* Awh = g_Wh + (size_t)(h * SQ + rowBase) * SQ;
    const __nv_bfloat16* Awl = g_Wl + (size_t)(h * SQ + rowBase) * SQ;
    const __nv_bfloat16* Bvh = g_Vth + (size_t)h * HD * SQ;
    const __nv_bfloat16* Bvl = g_Vtl + (size_t)h * HD * SQ;

    auto issue = [&](int c) {
        const uint32_t slot = sb + (uint32_t)(c & 3) * SLOT_CTX;
#pragma unroll
        for (int it = 0; it < 2; it++) {
            const int id = it * 256 + tid;
            const int r = id >> 2, jc = id & 3;
            const int js = (jc + ((r >> 1) & 3)) & 3;
            const uint32_t so = (uint32_t)(r * 64 + js * 16);
            const size_t go = (size_t)r * SQ + c * 32 + jc * 8;
            cpa16(slot + so,        Awh + go);
            cpa16(slot + 8192 + so, Awl + go);
        }
        {
            const int r = tid >> 2, jc = tid & 3;
            const int js = (jc + ((r >> 1) & 3)) & 3;
            const uint32_t so = (uint32_t)(r * 64 + js * 16);
            const size_t go = (size_t)r * SQ + c * 32 + jc * 8;
            cpa16(slot + 16384 + so, Bvh + go);
            cpa16(slot + 20480 + so, Bvl + go);
        }
        cp_commit();
    };

    float acc[2][4][4];
#pragma unroll
    for (int a = 0; a < 2; a++)
#pragma unroll
        for (int b = 0; b < 4; b++)
#pragma unroll
            for (int c = 0; c < 4; c++) acc[a][b][c] = 0.f;

    issue(0); issue(1); issue(2);

    const int aR0 = l & 15, aJ = l >> 4;
    const int bR0 = ((l >> 4) << 3) + (l & 7), bJ = (l >> 3) & 1;

    for (int c = 0; c < 64; c++) {
        if (c <= 61)      cp_wait<2>();
        else if (c == 62) cp_wait<1>();
        else              cp_wait<0>();
        __syncthreads();
        const uint32_t slot = sb + (uint32_t)(c & 3) * SLOT_CTX;
#pragma unroll
        for (int kk = 0; kk < 2; kk++) {
            uint32_t ah[2][4], al_[2][4], bh_[2][4], bl_[2][4];
#pragma unroll
            for (int mi = 0; mi < 2; mi++) {
                const int R = mW + mi * 16 + aR0;
                const int j = (kk << 1) | aJ;
                const int js = (j + ((R >> 1) & 3)) & 3;
                const uint32_t off = (uint32_t)(R * 64 + js * 16);
                ldm4(ah[mi],  slot + off);
                ldm4(al_[mi], slot + 8192 + off);
            }
#pragma unroll
            for (int np = 0; np < 2; np++) {
                const int R = nW + np * 16 + bR0;
                const int j = (kk << 1) | bJ;
                const int js = (j + ((R >> 1) & 3)) & 3;
                const uint32_t off = (uint32_t)(R * 64 + js * 16);
                ldm4(bh_[np], slot + 16384 + off);
                ldm4(bl_[np], slot + 20480 + off);
            }
#pragma unroll
            for (int mi = 0; mi < 2; mi++)
#pragma unroll
                for (int ni = 0; ni < 4; ni++) {
                    const int np = ni >> 1, q = (ni & 1) * 2;
                    uint32_t bhf[2] = { bh_[np][q], bh_[np][q + 1] };
                    uint32_t blf[2] = { bl_[np][q], bl_[np][q + 1] };
                    mma16(acc[mi][ni], ah[mi], bhf);
                    mma16(acc[mi][ni], ah[mi], blf);
                    mma16(acc[mi][ni], al_[mi], bhf);
                }
        }
        if (c + 3 < 64) issue(c + 3);
    }

    const int g = l >> 2, tg = l & 3;
#pragma unroll
    for (int mi = 0; mi < 2; mi++) {
#pragma unroll
        for (int ni = 0; ni < 4; ni++) {
            const int d0 = nW + ni * 8 + 2 * tg;
#pragma unroll
            for (int half = 0; half < 2; half++) {
                const int s = rowBase + mW + mi * 16 + g + half * 8;
                const float c0 = acc[mi][ni][half * 2 + 0];
                const float c1 = acc[mi][ni][half * 2 + 1];
                __nv_bfloat162 hh = __floats2bfloat162_rn(c0, c1);
                float2 ff = __bfloat1622float2(hh);
                __nv_bfloat162 ll = __floats2bfloat162_rn(c0 - ff.x, c1 - ff.y);
                const size_t idx = (size_t)s * HID + h * HD + d0;
                *(__nv_bfloat162*)(g_Ctxh + idx) = hh;
                *(__nv_bfloat162*)(g_Ctxl + idx) = ll;
            }
        }
    }
}

// =======================================================================
// K6: output = Ctx @ Wo^T + bo. ring engine. grid (6, 16), 256 thr
// =======================================================================
__global__ __launch_bounds__(256) void k_outproj(const float* __restrict__ bo,
                                                 float* __restrict__ out)
{
    const int rowBase = blockIdx.y * 128;
    const int colBase = blockIdx.x * 128;

    float acc[4][4][4];
#pragma unroll
    for (int a = 0; a < 4; a++)
#pragma unroll
        for (int b = 0; b < 4; b++)
#pragma unroll
            for (int c = 0; c < 4; c++) acc[a][b][c] = 0.f;

    tc_abt_ring(g_Ctxh + (size_t)rowBase * HID, g_Ctxl + (size_t)rowBase * HID,
                g_Wbh + (size_t)3 * NW + (size_t)colBase * HID,
                g_Wbl + (size_t)3 * NW + (size_t)colBase * HID,
                HID, HID / 32, acc);

    const int w = threadIdx.x >> 5, l = threadIdx.x & 31;
    const int g = l >> 2, tg = l & 3;
    const int mW = (w >> 2) * 64, nW = (w & 3) * 32;
#pragma unroll
    for (int mi = 0; mi < 4; mi++) {
#pragma unroll
        for (int ni = 0; ni < 4; ni++) {
            const int o0 = colBase + nW + ni * 8 + 2 * tg;
            const float b0 = bo[o0], b1 = bo[o0 + 1];
#pragma unroll
            for (int half = 0; half < 2; half++) {
                const int s = rowBase + mW + mi * 16 + g + half * 8;
                float2 v = make_float2(acc[mi][ni][half * 2 + 0] + b0,
                                       acc[mi][ni][half * 2 + 1] + b1);
                *(float2*)(out + (size_t)s * HID + o0) = v;
            }
        }
    }
}

// =======================================================================
extern "C" void kernel_launch(void* const* d_in, const int* in_sizes, int n_in,
                              void* d_out, int out_size)
{
    const float* X    = (const float*)d_in[0];
    const float* mask = (const float*)d_in[1];
    const float* Wq   = (const float*)d_in[2];
    const float* bq   = (const float*)d_in[3];
    const float* Wk   = (const float*)d_in[4];
    const float* bk   = (const float*)d_in[5];
    const float* Wv   = (const float*)d_in[6];
    const float* bv   = (const float*)d_in[7];
    const float* Wo   = (const float*)d_in[8];
    const float* bo   = (const float*)d_in[9];
    const float* omega = (const float*)d_in[10];
    const float* rffb  = (const float*)d_in[11];

    float* out = (float*)d_out;
    float* wts = (out_size > SQ * HID) ? (out + (size_t)SQ * HID) : nullptr;

    cudaFuncSetAttribute(k_qkv,     cudaFuncAttributeMaxDynamicSharedMemorySize, (int)SMEM_PR);
    cudaFuncSetAttribute(k_outproj, cudaFuncAttributeMaxDynamicSharedMemorySize, (int)SMEM_PR);
    cudaFuncSetAttribute(k_scores,  cudaFuncAttributeMaxDynamicSharedMemorySize, (int)SMEM_SC2);
    cudaFuncSetAttribute(k_context, cudaFuncAttributeMaxDynamicSharedMemorySize, (int)SMEM_CTX);

    k_prep<<<(PREP_N4 + 255) / 256, 256>>>(X, Wq, Wk, Wv, Wo);
    k_qkv<<<dim3(HID / 128, SQ / 128, 3), 256, SMEM_PR>>>(bq, bk, bv);
    k_phi<<<dim3(SQ / PHI_ROWS, NH, 2), 128>>>(omega, rffb);
    k_scores<<<dim3(SQ / 256, SQ / 128, NH), 256, SMEM_SC2>>>(mask, wts);
    k_softmax<<<dim3(NH * SQ), 256>>>(wts);
    k_context<<<dim3(SQ / 128, NH), 256, SMEM_CTX>>>();
    k_outproj<<<dim3(HID / 128, SQ / 128), 256, SMEM_PR>>>(bo, out);
}

// round 13
// speedup vs baseline: 1.5436x; 1.5436x over previous
#include <cuda_runtime.h>
#include <cuda_bf16.h>
#include <math.h>
#include <stdint.h>

#define SQ   2048
#define HID  768
#define NH   12
#define HD   64
#define NF   128
#define KE   192
#define NW   (HID * HID)

// ring engine: 3 slots x (Ah/Al/Bh/Bl 8K each)
#define SLOT_PR   32768
#define SMEM_PR   (3 * SLOT_PR)                  // 98304
// context kernel v2 (64-row tiles): 4 slots x (Ah 4K + Al 4K + Vh 4K + Vl 4K)
#define SLOT_CTX  16384
#define SMEM_CTX  (4 * SLOT_CTX)                 // 65536

// ---------------- device scratch ----------------
__device__ float g_Q [NH * SQ * HD];
__device__ float g_K [NH * SQ * HD];
__device__ __align__(16) __nv_bfloat16 g_Xh [SQ * HID];
__device__ __align__(16) __nv_bfloat16 g_Xl [SQ * HID];
__device__ __align__(16) __nv_bfloat16 g_Wbh[4 * NW];     // Wq,Wk,Wv,Wo hi
__device__ __align__(16) __nv_bfloat16 g_Wbl[4 * NW];     // lo
__device__ __align__(16) __nv_bfloat16 g_Qeh[NH * SQ * KE];
__device__ __align__(16) __nv_bfloat16 g_Qel[NH * SQ * KE];
__device__ __align__(16) __nv_bfloat16 g_Keh[NH * SQ * KE];
__device__ __align__(16) __nv_bfloat16 g_Kel[NH * SQ * KE];
__device__ __align__(16) __nv_bfloat16 g_Vth[NH * HD * SQ];
__device__ __align__(16) __nv_bfloat16 g_Vtl[NH * HD * SQ];
__device__ __align__(16) __nv_bfloat16 g_Wh [(size_t)NH * SQ * SQ];
__device__ __align__(16) __nv_bfloat16 g_Wl [(size_t)NH * SQ * SQ];
__device__ __align__(16) __nv_bfloat16 g_Ctxh[SQ * HID];
__device__ __align__(16) __nv_bfloat16 g_Ctxl[SQ * HID];
__device__ __align__(16) float g_Wsc[(size_t)NH * SQ * SQ];

// ---------------- low-level helpers ----------------
__device__ __forceinline__ uint32_t smem_u32(const void* p) {
    return (uint32_t)__cvta_generic_to_shared(p);
}
__device__ __forceinline__ void ldm4(uint32_t r[4], uint32_t addr) {
    asm volatile("ldmatrix.sync.aligned.m8n8.x4.shared.b16 {%0,%1,%2,%3}, [%4];"
                 : "=r"(r[0]), "=r"(r[1]), "=r"(r[2]), "=r"(r[3]) : "r"(addr));
}
__device__ __forceinline__ void mma16(float c[4], const uint32_t a[4], const uint32_t b[2]) {
    asm volatile(
        "mma.sync.aligned.m16n8k16.row.col.f32.bf16.bf16.f32 "
        "{%0,%1,%2,%3},{%4,%5,%6,%7},{%8,%9},{%0,%1,%2,%3};\n"
        : "+f"(c[0]), "+f"(c[1]), "+f"(c[2]), "+f"(c[3])
        : "r"(a[0]), "r"(a[1]), "r"(a[2]), "r"(a[3]), "r"(b[0]), "r"(b[1]));
}
__device__ __forceinline__ void cpa16(uint32_t saddr, const void* g) {
    asm volatile("cp.async.cg.shared.global [%0], [%1], 16;\n" :: "r"(saddr), "l"(g));
}
__device__ __forceinline__ void cp_commit() {
    asm volatile("cp.async.commit_group;\n");
}
template<int N> __device__ __forceinline__ void cp_wait() {
    asm volatile("cp.async.wait_group %0;\n" :: "n"(N));
}
__device__ __forceinline__ void split2(float v, __nv_bfloat16& h, __nv_bfloat16& l) {
    h = __float2bfloat16_rn(v);
    l = __float2bfloat16_rn(v - __bfloat162float(h));
}

// =======================================================================
// K0: prep — split X and the 4 weight matrices into bf16 hi/lo.
// =======================================================================
#define PREP_N4 ((SQ * HID + 4 * NW) / 4)
__global__ __launch_bounds__(256) void k_prep(const float* __restrict__ X,
    const float* __restrict__ Wq, const float* __restrict__ Wk,
    const float* __restrict__ Wv, const float* __restrict__ Wo)
{
    const int i = blockIdx.x * 256 + threadIdx.x;
    if (i >= PREP_N4) return;
    const int NX4 = SQ * HID / 4, NW4 = NW / 4;
    const float* src;
    __nv_bfloat16 *dh, *dl;
    int j = i;
    if (j < NX4) { src = X; dh = g_Xh; dl = g_Xl; }
    else {
        j -= NX4;
        const int z = j / NW4;
        j -= z * NW4;
        src = (z == 0) ? Wq : (z == 1) ? Wk : (z == 2) ? Wv : Wo;
        dh = g_Wbh + (size_t)z * NW; dl = g_Wbl + (size_t)z * NW;
    }
    float4 v = *(const float4*)(src + (size_t)j * 4);
    __nv_bfloat162 h01 = __floats2bfloat162_rn(v.x, v.y);
    __nv_bfloat162 h23 = __floats2bfloat162_rn(v.z, v.w);
    float2 f01 = __bfloat1622float2(h01), f23 = __bfloat1622float2(h23);
    *(__nv_bfloat162*)(dh + (size_t)j * 4)     = h01;
    *(__nv_bfloat162*)(dh + (size_t)j * 4 + 2) = h23;
    *(__nv_bfloat162*)(dl + (size_t)j * 4)     = __floats2bfloat162_rn(v.x - f01.x, v.y - f01.y);
    *(__nv_bfloat162*)(dl + (size_t)j * 4 + 2) = __floats2bfloat162_rn(v.z - f23.x, v.w - f23.y);
}

// =======================================================================
// Generic pre-split bf16 ABt ring engine. 3 slots, prefetch distance 2.
// block 128x128, 8 warps (2m x 4n), warp tile 64x32.
// =======================================================================
__device__ __forceinline__ void tc_abt_ring(const __nv_bfloat16* __restrict__ Agh,
                                            const __nv_bfloat16* __restrict__ Agl,
                                            const __nv_bfloat16* __restrict__ Bgh,
                                            const __nv_bfloat16* __restrict__ Bgl,
                                            int ld, int nCh,
                                            float acc[4][4][4])
{
    extern __shared__ char smc[];
    const int tid = threadIdx.x, w = tid >> 5, l = tid & 31;
    const int mW = (w >> 2) * 64, nW = (w & 3) * 32;
    const uint32_t sb = smem_u32(smc);

    auto issue = [&](int c) {
        const uint32_t slot = sb + (uint32_t)(c % 3) * SLOT_PR;
#pragma unroll
        for (int it = 0; it < 2; it++) {
            const int id = it * 256 + tid;
            const int r = id >> 2, jc = id & 3;
            const int js = (jc + ((r >> 1) & 3)) & 3;
            const uint32_t so = (uint32_t)(r * 64 + js * 16);
            const size_t go = (size_t)r * ld + c * 32 + jc * 8;
            cpa16(slot + so,         Agh + go);
            cpa16(slot + 8192 + so,  Agl + go);
            cpa16(slot + 16384 + so, Bgh + go);
            cpa16(slot + 24576 + so, Bgl + go);
        }
        cp_commit();
    };

    issue(0); issue(1);

    const int aR0 = l & 15, aJ = l >> 4;
    const int bR0 = ((l >> 4) << 3) + (l & 7), bJ = (l >> 3) & 1;

    for (int c = 0; c < nCh; c++) {
        if (c <= nCh - 2) cp_wait<1>();
        else              cp_wait<0>();
        __syncthreads();
        const uint32_t slot = sb + (uint32_t)(c % 3) * SLOT_PR;
#pragma unroll
        for (int kk = 0; kk < 2; kk++) {
            uint32_t ah[4][4], al_[4][4], bh_[2][4], bl_[2][4];
#pragma unroll
            for (int mi = 0; mi < 4; mi++) {
                const int R = mW + mi * 16 + aR0;
                const int j = (kk << 1) | aJ;
                const int js = (j + ((R >> 1) & 3)) & 3;
                const uint32_t off = (uint32_t)(R * 64 + js * 16);
                ldm4(ah[mi],  slot + off);
                ldm4(al_[mi], slot + 8192 + off);
            }
#pragma unroll
            for (int np = 0; np < 2; np++) {
                const int R = nW + np * 16 + bR0;
                const int j = (kk << 1) | bJ;
                const int js = (j + ((R >> 1) & 3)) & 3;
                const uint32_t off = (uint32_t)(R * 64 + js * 16);
                ldm4(bh_[np], slot + 16384 + off);
                ldm4(bl_[np], slot + 24576 + off);
            }
#pragma unroll
            for (int mi = 0; mi < 4; mi++)
#pragma unroll
                for (int ni = 0; ni < 4; ni++) {
                    const int np = ni >> 1, q = (ni & 1) * 2;
                    uint32_t bhf[2] = { bh_[np][q], bh_[np][q + 1] };
                    uint32_t blf[2] = { bl_[np][q], bl_[np][q + 1] };
                    mma16(acc[mi][ni], ah[mi], bhf);
                    mma16(acc[mi][ni], ah[mi], blf);
                    mma16(acc[mi][ni], al_[mi], bhf);
                }
        }
        if (c + 2 < nCh) issue(c + 2);
    }
}

// =======================================================================
// K1: QKV projections. z=0:Q 1:K 2:V. grid (6,16,3), 256 thr
// =======================================================================
__global__ __launch_bounds__(256) void k_qkv(const float* __restrict__ bq,
    const float* __restrict__ bk, const float* __restrict__ bv)
{
    const int z = blockIdx.z;
    const float* bias = (z == 0) ? bq : (z == 1) ? bk : bv;
    const int rowBase = blockIdx.y * 128;
    const int colBase = blockIdx.x * 128;

    float acc[4][4][4];
#pragma unroll
    for (int a = 0; a < 4; a++)
#pragma unroll
        for (int b = 0; b < 4; b++)
#pragma unroll
            for (int c = 0; c < 4; c++) acc[a][b][c] = 0.f;

    tc_abt_ring(g_Xh + (size_t)rowBase * HID, g_Xl + (size_t)rowBase * HID,
                g_Wbh + (size_t)z * NW + (size_t)colBase * HID,
                g_Wbl + (size_t)z * NW + (size_t)colBase * HID,
                HID, HID / 32, acc);

    const int w = threadIdx.x >> 5, l = threadIdx.x & 31;
    const int g = l >> 2, tg = l & 3;
    const int mW = (w >> 2) * 64, nW = (w & 3) * 32;
#pragma unroll
    for (int mi = 0; mi < 4; mi++) {
#pragma unroll
        for (int ni = 0; ni < 4; ni++) {
#pragma unroll
            for (int cr = 0; cr < 4; cr++) {
                const int s = rowBase + mW + mi * 16 + g + ((cr >> 1) << 3);
                const int o = colBase + nW + ni * 8 + 2 * tg + (cr & 1);
                const float v = acc[mi][ni][cr] + bias[o];
                const int h = o >> 6, d = o & 63;
                if (z == 2) {
                    __nv_bfloat16 hi, lo; split2(v, hi, lo);
                    const size_t idx = ((size_t)h * HD + d) * SQ + s;
                    g_Vth[idx] = hi; g_Vtl[idx] = lo;
                } else if (z == 1) g_K[((size_t)h * SQ + s) * HD + d] = v;
                else               g_Q[((size_t)h * SQ + s) * HD + d] = v;
            }
        }
    }
}

// =======================================================================
// K2: RFF features. 16 rows/block, 2 syncs/row. grid (128, NH, 2), 128 thr
// =======================================================================
#define OMLD 129
#define PHI_ROWS 16

__global__ __launch_bounds__(128) void k_phi(const float* __restrict__ omega,
                                             const float* __restrict__ rffb)
{
    __shared__ float omT[HD * OMLD];
    __shared__ float qrow[2][HD];
    __shared__ float red[2][4];

    const int tid  = threadIdx.x;
    const int h    = blockIdx.y;
    const int side = blockIdx.z;
    const int lane = tid & 31, wrp = tid >> 5;

    for (int i = tid; i < NF * HD; i += 128) {
        const int f = i >> 6, d = i & 63;
        omT[d * OMLD + f] = omega[((size_t)h * NF + f) * HD + d];
    }
    const float bf = rffb[h * NF + tid];
    const float* src = (side ? g_K : g_Q) + (size_t)h * SQ * HD;
    __nv_bfloat16* eh = (side ? g_Keh : g_Qeh) + (size_t)h * SQ * KE;
    __nv_bfloat16* el = (side ? g_Kel : g_Qel) + (size_t)h * SQ * KE;
    const float qscale   = side ? 1.0f : 0.1125f;
    const float segscale = side ? 1.0f : 0.1f;

    for (int r = 0; r < PHI_ROWS; r++) {
        const int s = blockIdx.x * PHI_ROWS + r;
        const int p = r & 1;
        if (tid < 64) qrow[p][tid] = src[(size_t)s * HD + tid];
        __syncthreads();

        float dot = 0.f, qss = 0.f;
#pragma unroll 8
        for (int d = 0; d < HD; d++) {
            const float qd = qrow[p][d];
            dot += qd * omT[d * OMLD + tid];
            qss += qd * qd;
        }
        const float inv = 1.0f / (sqrtf(qss) + 1e-5f);
        const float zv = inv * dot + bf;
        const float ph = 0.125f * __cosf(zv);

        float v = ph * ph;
        for (int o = 16; o > 0; o >>= 1) v += __shfl_xor_sync(0xffffffffu, v, o);
        if (lane == 0) red[p][wrp] = v;
        __syncthreads();
        const float pn2 = red[p][0] + red[p][1] + red[p][2] + red[p][3];

        const float outv = (ph / (sqrtf(pn2) + 1e-6f)) * segscale;
        __nv_bfloat16 hi, lo;
        split2(outv, hi, lo);
        eh[(size_t)s * KE + HD + tid] = hi;
        el[(size_t)s * KE + HD + tid] = lo;
        if (tid < 64) {
            split2(qrow[p][tid] * qscale, hi, lo);
            eh[(size_t)s * KE + tid] = hi;
            el[(size_t)s * KE + tid] = lo;
        }
    }
}

// =======================================================================
// K3: scores = Qe . Ke^T + mask. Mixed-precision ring (R10 version).
// chunks 0-1 hi/lo 3-term, chunks 2-5 single bf16. grid (16,16,12), 256 thr
// =======================================================================
__global__ __launch_bounds__(256) void k_scores(const float* __restrict__ mask,
                                                float* wts)
{
    extern __shared__ char smc[];
    float* W = wts ? wts : g_Wsc;
    const int h = blockIdx.z;
    const int rowBase = blockIdx.y * 128;
    const int colBase = blockIdx.x * 128;
    const int tid = threadIdx.x, w = tid >> 5, l = tid & 31;
    const int mW = (w >> 2) * 64, nW = (w & 3) * 32;
    const uint32_t sb = smem_u32(smc);

    const __nv_bfloat16* Agh = g_Qeh + (size_t)(h * SQ + rowBase) * KE;
    const __nv_bfloat16* Agl = g_Qel + (size_t)(h * SQ + rowBase) * KE;
    const __nv_bfloat16* Bgh = g_Keh + (size_t)(h * SQ + colBase) * KE;
    const __nv_bfloat16* Bgl = g_Kel + (size_t)(h * SQ + colBase) * KE;

    auto issue = [&](int c) {
        const uint32_t slot = sb + (uint32_t)(c % 3) * SLOT_PR;
#pragma unroll
        for (int it = 0; it < 2; it++) {
            const int id = it * 256 + tid;
            const int r = id >> 2, jc = id & 3;
            const int js = (jc + ((r >> 1) & 3)) & 3;
            const uint32_t so = (uint32_t)(r * 64 + js * 16);
            const size_t go = (size_t)r * KE + c * 32 + jc * 8;
            cpa16(slot + so,         Agh + go);
            cpa16(slot + 16384 + so, Bgh + go);
            if (c < 2) {
                cpa16(slot + 8192 + so,  Agl + go);
                cpa16(slot + 24576 + so, Bgl + go);
            }
        }
        cp_commit();
    };

    issue(0); issue(1);

    float acc[4][4][4];
#pragma unroll
    for (int a = 0; a < 4; a++)
#pragma unroll
        for (int b = 0; b < 4; b++)
#pragma unroll
            for (int c = 0; c < 4; c++) acc[a][b][c] = 0.f;

    const int aR0 = l & 15, aJ = l >> 4;
    const int bR0 = ((l >> 4) << 3) + (l & 7), bJ = (l >> 3) & 1;

    for (int c = 0; c < 6; c++) {
        if (c <= 4) cp_wait<1>();
        else        cp_wait<0>();
        __syncthreads();
        const uint32_t slot = sb + (uint32_t)(c % 3) * SLOT_PR;
#pragma unroll
        for (int kk = 0; kk < 2; kk++) {
            uint32_t ah[4][4], bh_[2][4];
#pragma unroll
            for (int mi = 0; mi < 4; mi++) {
                const int R = mW + mi * 16 + aR0;
                const int j = (kk << 1) | aJ;
                const int js = (j + ((R >> 1) & 3)) & 3;
                ldm4(ah[mi], slot + (uint32_t)(R * 64 + js * 16));
            }
#pragma unroll
            for (int np = 0; np < 2; np++) {
                const int R = nW + np * 16 + bR0;
                const int j = (kk << 1) | bJ;
                const int js = (j + ((R >> 1) & 3)) & 3;
                ldm4(bh_[np], slot + 16384 + (uint32_t)(R * 64 + js * 16));
            }
            if (c < 2) {
                uint32_t al_[4][4], bl_[2][4];
#pragma unroll
                for (int mi = 0; mi < 4; mi++) {
                    const int R = mW + mi * 16 + aR0;
                    const int j = (kk << 1) | aJ;
                    const int js = (j + ((R >> 1) & 3)) & 3;
                    ldm4(al_[mi], slot + 8192 + (uint32_t)(R * 64 + js * 16));
                }
#pragma unroll
                for (int np = 0; np < 2; np++) {
                    const int R = nW + np * 16 + bR0;
                    const int j = (kk << 1) | bJ;
                    const int js = (j + ((R >> 1) & 3)) & 3;
                    ldm4(bl_[np], slot + 24576 + (uint32_t)(R * 64 + js * 16));
                }
#pragma unroll
                for (int mi = 0; mi < 4; mi++)
#pragma unroll
                    for (int ni = 0; ni < 4; ni++) {
                        const int np = ni >> 1, q = (ni & 1) * 2;
                        uint32_t bhf[2] = { bh_[np][q], bh_[np][q + 1] };
                        uint32_t blf[2] = { bl_[np][q], bl_[np][q + 1] };
                        mma16(acc[mi][ni], ah[mi], bhf);
                        mma16(acc[mi][ni], ah[mi], blf);
                        mma16(acc[mi][ni], al_[mi], bhf);
                    }
            } else {
#pragma unroll
                for (int mi = 0; mi < 4; mi++)
#pragma unroll
                    for (int ni = 0; ni < 4; ni++) {
                        const int np = ni >> 1, q = (ni & 1) * 2;
                        uint32_t bhf[2] = { bh_[np][q], bh_[np][q + 1] };
                        mma16(acc[mi][ni], ah[mi], bhf);
                    }
            }
        }
        if (c + 2 < 6) issue(c + 2);
    }

    float* Wh = W + (size_t)h * SQ * SQ;
    const int g = l >> 2, tg = l & 3;
#pragma unroll
    for (int mi = 0; mi < 4; mi++) {
#pragma unroll
        for (int ni = 0; ni < 4; ni++) {
            const int t0 = colBase + nW + ni * 8 + 2 * tg;
            const float mk0 = (mask[t0] - 1.0f) * 10000.0f;
            const float mk1 = (mask[t0 + 1] - 1.0f) * 10000.0f;
#pragma unroll
            for (int half = 0; half < 2; half++) {
                const int s = rowBase + mW + mi * 16 + g + half * 8;
                float2 v = make_float2(acc[mi][ni][half * 2 + 0] + mk0,
                                       acc[mi][ni][half * 2 + 1] + mk1);
                *(float2*)(Wh + (size_t)s * SQ + t0) = v;
            }
        }
    }
}

// =======================================================================
// K4: row softmax, fp32 out + bf16 hi/lo copies. grid (NH*SQ), 256 thr
// =======================================================================
__global__ __launch_bounds__(256) void k_softmax(float* wts)
{
    __shared__ float red[8];
    float* W = wts ? wts : g_Wsc;
    float4* p = (float4*)(W + (size_t)blockIdx.x * SQ);
    __nv_bfloat16* wh = g_Wh + (size_t)blockIdx.x * SQ;
    __nv_bfloat16* wl = g_Wl + (size_t)blockIdx.x * SQ;
    const int tid = threadIdx.x;

    float4 v0 = p[tid];
    float4 v1 = p[tid + 256];
    float m = fmaxf(fmaxf(fmaxf(v0.x, v0.y), fmaxf(v0.z, v0.w)),
                    fmaxf(fmaxf(v1.x, v1.y), fmaxf(v1.z, v1.w)));
    for (int o = 16; o > 0; o >>= 1) m = fmaxf(m, __shfl_xor_sync(0xffffffffu, m, o));
    if ((tid & 31) == 0) red[tid >> 5] = m;
    __syncthreads();
    m = red[0];
#pragma unroll
    for (int i = 1; i < 8; i++) m = fmaxf(m, red[i]);
    __syncthreads();

    v0.x = __expf(v0.x - m); v0.y = __expf(v0.y - m);
    v0.z = __expf(v0.z - m); v0.w = __expf(v0.w - m);
    v1.x = __expf(v1.x - m); v1.y = __expf(v1.y - m);
    v1.z = __expf(v1.z - m); v1.w = __expf(v1.w - m);
    float s = v0.x + v0.y + v0.z + v0.w + v1.x + v1.y + v1.z + v1.w;
    for (int o = 16; o > 0; o >>= 1) s += __shfl_xor_sync(0xffffffffu, s, o);
    if ((tid & 31) == 0) red[tid >> 5] = s;
    __syncthreads();
    s = red[0] + red[1] + red[2] + red[3] + red[4] + red[5] + red[6] + red[7];
    const float inv = 1.0f / s;

    v0.x *= inv; v0.y *= inv; v0.z *= inv; v0.w *= inv;
    v1.x *= inv; v1.y *= inv; v1.z *= inv; v1.w *= inv;
    p[tid] = v0;
    p[tid + 256] = v1;

    {
        __nv_bfloat162 h01 = __floats2bfloat162_rn(v0.x, v0.y);
        __nv_bfloat162 h23 = __floats2bfloat162_rn(v0.z, v0.w);
        float2 f01 = __bfloat1622float2(h01), f23 = __bfloat1622float2(h23);
        *(__nv_bfloat162*)(wh + tid * 4)     = h01;
        *(__nv_bfloat162*)(wh + tid * 4 + 2) = h23;
        *(__nv_bfloat162*)(wl + tid * 4)     = __floats2bfloat162_rn(v0.x - f01.x, v0.y - f01.y);
        *(__nv_bfloat162*)(wl + tid * 4 + 2) = __floats2bfloat162_rn(v0.z - f23.x, v0.w - f23.y);
        h01 = __floats2bfloat162_rn(v1.x, v1.y);
        h23 = __floats2bfloat162_rn(v1.z, v1.w);
        f01 = __bfloat1622float2(h01); f23 = __bfloat1622float2(h23);
        *(__nv_bfloat162*)(wh + (tid + 256) * 4)     = h01;
        *(__nv_bfloat162*)(wh + (tid + 256) * 4 + 2) = h23;
        *(__nv_bfloat162*)(wl + (tid + 256) * 4)     = __floats2bfloat162_rn(v1.x - f01.x, v1.y - f01.y);
        *(__nv_bfloat162*)(wl + (tid + 256) * 4 + 2) = __floats2bfloat162_rn(v1.z - f23.x, v1.w - f23.y);
    }
}

// =======================================================================
// K5 v2: context = W . Vt^T -> bf16 hi/lo Ctx. 64-row tiles for balance.
// 4-slot ring (slot = Ah 4K + Al 4K + Vh 4K + Vl 4K). grid (32, NH), 256 thr
// 8 warps = 4m x 2n, warp tile 16x32.
// =======================================================================
__global__ __launch_bounds__(256) void k_context()
{
    extern __shared__ char smc[];
    const int h = blockIdx.y;
    const int rowBase = blockIdx.x * 64;
    const int tid = threadIdx.x, w = tid >> 5, l = tid & 31;
    const int mW = (w >> 1) * 16, nW = (w & 1) * 32;
    const uint32_t sb = smem_u32(smc);

    const __nv_bfloat16* Awh = g_Wh + (size_t)(h * SQ + rowBase) * SQ;
    const __nv_bfloat16* Awl = g_Wl + (size_t)(h * SQ + rowBase) * SQ;
    const __nv_bfloat16* Bvh = g_Vth + (size_t)h * HD * SQ;
    const __nv_bfloat16* Bvl = g_Vtl + (size_t)h * HD * SQ;

    auto issue = [&](int c) {
        const uint32_t slot = sb + (uint32_t)(c & 3) * SLOT_CTX;
        const int r = tid >> 2, jc = tid & 3;        // 64 rows x 4 groups
        const int js = (jc + ((r >> 1) & 3)) & 3;
        const uint32_t so = (uint32_t)(r * 64 + js * 16);
        const size_t go = (size_t)r * SQ + c * 32 + jc * 8;
        cpa16(slot + so,         Awh + go);
        cpa16(slot + 4096 + so,  Awl + go);
        cpa16(slot + 8192 + so,  Bvh + go);
        cpa16(slot + 12288 + so, Bvl + go);
        cp_commit();
    };

    float acc[4][4];
#pragma unroll
    for (int b = 0; b < 4; b++)
#pragma unroll
        for (int c = 0; c < 4; c++) acc[b][c] = 0.f;

    issue(0); issue(1); issue(2);

    const int aR0 = l & 15, aJ = l >> 4;
    const int bR0 = ((l >> 4) << 3) + (l & 7), bJ = (l >> 3) & 1;

    for (int c = 0; c < 64; c++) {
        if (c <= 61)      cp_wait<2>();
        else if (c == 62) cp_wait<1>();
        else              cp_wait<0>();
        __syncthreads();
        const uint32_t slot = sb + (uint32_t)(c & 3) * SLOT_CTX;
#pragma unroll
        for (int kk = 0; kk < 2; kk++) {
            uint32_t ah[4], al_[4], bh_[2][4], bl_[2][4];
            {
                const int R = mW + aR0;
                const int j = (kk << 1) | aJ;
                const int js = (j + ((R >> 1) & 3)) & 3;
                const uint32_t off = (uint32_t)(R * 64 + js * 16);
                ldm4(ah,  slot + off);
                ldm4(al_, slot + 4096 + off);
            }
#pragma unroll
            for (int np = 0; np < 2; np++) {
                const int R = nW + np * 16 + bR0;
                const int j = (kk << 1) | bJ;
                const int js = (j + ((R >> 1) & 3)) & 3;
                const uint32_t off = (uint32_t)(R * 64 + js * 16);
                ldm4(bh_[np], slot + 8192 + off);
                ldm4(bl_[np], slot + 12288 + off);
            }
#pragma unroll
            for (int ni = 0; ni < 4; ni++) {
                const int np = ni >> 1, q = (ni & 1) * 2;
                uint32_t bhf[2] = { bh_[np][q], bh_[np][q + 1] };
                uint32_t blf[2] = { bl_[np][q], bl_[np][q + 1] };
                mma16(acc[ni], ah,  bhf);
                mma16(acc[ni], ah,  blf);
                mma16(acc[ni], al_, bhf);
            }
        }
        if (c + 3 < 64) issue(c + 3);
    }

    const int g = l >> 2, tg = l & 3;
#pragma unroll
    for (int ni = 0; ni < 4; ni++) {
        const int d0 = nW + ni * 8 + 2 * tg;
#pragma unroll
        for (int half = 0; half < 2; half++) {
            const int s = rowBase + mW + g + half * 8;
            const float c0 = acc[ni][half * 2 + 0];
            const float c1 = acc[ni][half * 2 + 1];
            __nv_bfloat162 hh = __floats2bfloat162_rn(c0, c1);
            float2 ff = __bfloat1622float2(hh);
            __nv_bfloat162 ll = __floats2bfloat162_rn(c0 - ff.x, c1 - ff.y);
            const size_t idx = (size_t)s * HID + h * HD + d0;
            *(__nv_bfloat162*)(g_Ctxh + idx) = hh;
            *(__nv_bfloat162*)(g_Ctxl + idx) = ll;
        }
    }
}

// =======================================================================
// K6: output = Ctx @ Wo^T + bo. ring engine. grid (6, 16), 256 thr
// =======================================================================
__global__ __launch_bounds__(256) void k_outproj(const float* __restrict__ bo,
                                                 float* __restrict__ out)
{
    const int rowBase = blockIdx.y * 128;
    const int colBase = blockIdx.x * 128;

    float acc[4][4][4];
#pragma unroll
    for (int a = 0; a < 4; a++)
#pragma unroll
        for (int b = 0; b < 4; b++)
#pragma unroll
            for (int c = 0; c < 4; c++) acc[a][b][c] = 0.f;

    tc_abt_ring(g_Ctxh + (size_t)rowBase * HID, g_Ctxl + (size_t)rowBase * HID,
                g_Wbh + (size_t)3 * NW + (size_t)colBase * HID,
                g_Wbl + (size_t)3 * NW + (size_t)colBase * HID,
                HID, HID / 32, acc);

    const int w = threadIdx.x >> 5, l = threadIdx.x & 31;
    const int g = l >> 2, tg = l & 3;
    const int mW = (w >> 2) * 64, nW = (w & 3) * 32;
#pragma unroll
    for (int mi = 0; mi < 4; mi++) {
#pragma unroll
        for (int ni = 0; ni < 4; ni++) {
            const int o0 = colBase + nW + ni * 8 + 2 * tg;
            const float b0 = bo[o0], b1 = bo[o0 + 1];
#pragma unroll
            for (int half = 0; half < 2; half++) {
                const int s = rowBase + mW + mi * 16 + g + half * 8;
                float2 v = make_float2(acc[mi][ni][half * 2 + 0] + b0,
                                       acc[mi][ni][half * 2 + 1] + b1);
                *(float2*)(out + (size_t)s * HID + o0) = v;
            }
        }
    }
}

// =======================================================================
extern "C" void kernel_launch(void* const* d_in, const int* in_sizes, int n_in,
                              void* d_out, int out_size)
{
    const float* X    = (const float*)d_in[0];
    const float* mask = (const float*)d_in[1];
    const float* Wq   = (const float*)d_in[2];
    const float* bq   = (const float*)d_in[3];
    const float* Wk   = (const float*)d_in[4];
    const float* bk   = (const float*)d_in[5];
    const float* Wv   = (const float*)d_in[6];
    const float* bv   = (const float*)d_in[7];
    const float* Wo   = (const float*)d_in[8];
    const float* bo   = (const float*)d_in[9];
    const float* omega = (const float*)d_in[10];
    const float* rffb  = (const float*)d_in[11];

    float* out = (float*)d_out;
    float* wts = (out_size > SQ * HID) ? (out + (size_t)SQ * HID) : nullptr;

    cudaFuncSetAttribute(k_qkv,     cudaFuncAttributeMaxDynamicSharedMemorySize, (int)SMEM_PR);
    cudaFuncSetAttribute(k_outproj, cudaFuncAttributeMaxDynamicSharedMemorySize, (int)SMEM_PR);
    cudaFuncSetAttribute(k_scores,  cudaFuncAttributeMaxDynamicSharedMemorySize, (int)SMEM_PR);
    cudaFuncSetAttribute(k_context, cudaFuncAttributeMaxDynamicSharedMemorySize, (int)SMEM_CTX);

    k_prep<<<(PREP_N4 + 255) / 256, 256>>>(X, Wq, Wk, Wv, Wo);
    k_qkv<<<dim3(HID / 128, SQ / 128, 3), 256, SMEM_PR>>>(bq, bk, bv);
    k_phi<<<dim3(SQ / PHI_ROWS, NH, 2), 128>>>(omega, rffb);
    k_scores<<<dim3(SQ / 128, SQ / 128, NH), 256, SMEM_PR>>>(mask, wts);
    k_softmax<<<dim3(NH * SQ), 256>>>(wts);
    k_context<<<dim3(SQ / 64, NH), 256, SMEM_CTX>>>();
    k_outproj<<<dim3(HID / 128, SQ / 128), 256, SMEM_PR>>>(bo, out);
}